// round 1
// baseline (speedup 1.0000x reference)
#include <cuda_runtime.h>

typedef unsigned long long ull;

#define D_IN 992
#define HID  32
#define W1   6
#define NB   12
#define KC   32      // k-chunk
#define RPB  128     // rows per block
#define NTHR 256

__device__ __forceinline__ ull ffma2(ull a, ull b, ull c) {
    ull d;
    asm("fma.rn.f32x2 %0, %1, %2, %3;" : "=l"(d) : "l"(a), "l"(b), "l"(c));
    return d;
}

__device__ __forceinline__ ull dupf(float f) {
    unsigned r = __float_as_uint(f);
    return (((ull)r) << 32) | (ull)r;
}

// Uniform-grid B-spline basis, G=8, K=4, grid pts t_j=(j-4)*0.25-1, j=0..16.
// After 4 Cox-de Boor passes, B[0..11] hold the degree-4 basis values.
__device__ __forceinline__ void basis12(float x, float B[16]) {
    float u = (x + 2.0f) * 4.0f;          // x in knot units from t_0
    int j0 = (int)floorf(u);
    #pragma unroll
    for (int j = 0; j < 16; j++) B[j] = (j == j0) ? 1.0f : 0.0f;
    #pragma unroll
    for (int p = 1; p <= 4; p++) {
        const float ip = 1.0f / (float)p;
        #pragma unroll
        for (int b = 0; b < 16 - p; b++)
            B[b] = ((u - (float)b) * B[b] + ((float)(b + p + 1) - u) * B[b + 1]) * ip;
    }
}

__device__ __forceinline__ float dot12(const float B[16], const float* __restrict__ c) {
    const float4* c4 = (const float4*)c;
    float4 a = c4[0], b = c4[1], d = c4[2];
    float s =      B[0]  * a.x;
    s = fmaf(B[1],  a.y, s); s = fmaf(B[2],  a.z, s); s = fmaf(B[3],  a.w, s);
    s = fmaf(B[4],  b.x, s); s = fmaf(B[5],  b.y, s); s = fmaf(B[6],  b.z, s);
    s = fmaf(B[7],  b.w, s); s = fmaf(B[8],  d.x, s); s = fmaf(B[9],  d.y, s);
    s = fmaf(B[10], d.z, s); s = fmaf(B[11], d.w, s);
    return s;
}

__device__ __forceinline__ float silu_f(float x) {
    return x / (1.0f + __expf(-x));
}

__global__ __launch_bounds__(NTHR, 2)
void kan_fused_kernel(const float* __restrict__ node_rep,
                      const float* __restrict__ mlp_w,
                      const float* __restrict__ mlp_b,
                      const float* __restrict__ coef0,
                      const float* __restrict__ wb0,
                      const float* __restrict__ ws0,
                      const float* __restrict__ b0,
                      const float* __restrict__ coef1,
                      const float* __restrict__ wb1,
                      const float* __restrict__ ws1,
                      const float* __restrict__ b1,
                      float* __restrict__ out, int n)
{
    // GEMM tiles (As + Wd) aliased with Hs (hidden buffer): GEMM region dead
    // once hidden is materialized.  24576 B >= 128*33*4 = 16896 B.
    __shared__ __align__(16) char buf[KC * RPB * 4 + KC * HID * 8];
    float (*As)[RPB]    = (float (*)[RPB])buf;                       // [KC][128]
    ull   (*Wd)[HID]    = (ull   (*)[HID])(buf + KC * RPB * 4);      // [KC][32] dup'd
    float (*Hs)[HID + 1] = (float (*)[HID + 1])buf;                  // [128][33]

    __shared__ __align__(16) float csc0[HID][W1][NB];   // coef0 * ws0
    __shared__ float wb0s[HID][W1];
    __shared__ float part[RPB][2][W1];
    __shared__ __align__(16) float csc1[W1][NB];        // coef1 * ws1
    __shared__ float wb1s[W1];
    __shared__ float b0s[W1];
    __shared__ float b1s;

    const int tid  = threadIdx.x;
    const int row0 = blockIdx.x * RPB;

    // ---- stage small params (prescale spline coefs by w_sp) ----
    for (int idx = tid; idx < HID * W1 * NB; idx += NTHR)
        (&csc0[0][0][0])[idx] = coef0[idx] * ws0[idx / NB];
    if (tid < HID * W1) (&wb0s[0][0])[tid] = wb0[tid];
    if (tid < W1 * NB)  (&csc1[0][0])[tid] = coef1[tid] * ws1[tid / NB];
    if (tid < W1) { wb1s[tid] = wb1[tid]; b0s[tid] = b0[tid]; }
    if (tid == 0) b1s = b1[0];

    // ---- GEMM: hidden[128][32] = node_rep_tile @ mlp_w ----
    const int og = tid & 15;   // output pair: cols og*2, og*2+1
    const int rg = tid >> 4;   // row group:   rows rg*8 .. rg*8+7
    ull acc[2][4];
    #pragma unroll
    for (int o = 0; o < 2; o++)
        #pragma unroll
        for (int r = 0; r < 4; r++) acc[o][r] = 0ull;

    for (int kc = 0; kc < D_IN; kc += KC) {
        __syncthreads();
        // load A tile (transposed): 32 k x 128 rows
        #pragma unroll
        for (int j = 0; j < 4; j++) {
            int idx = tid + NTHR * j;        // 0..1023 float4s
            int r   = idx >> 3;              // 8 float4 per row (32 k)
            int c   = idx & 7;
            float4 v = make_float4(0.f, 0.f, 0.f, 0.f);
            int grow = row0 + r;
            if (grow < n)
                v = *(const float4*)&node_rep[(size_t)grow * D_IN + kc + c * 4];
            As[c * 4 + 0][r] = v.x;
            As[c * 4 + 1][r] = v.y;
            As[c * 4 + 2][r] = v.z;
            As[c * 4 + 3][r] = v.w;
        }
        // load W tile, duplicated into both f32x2 lanes
        {
            int k = tid >> 3, c = tid & 7;   // 256 threads cover 32x32
            float4 v = *(const float4*)&mlp_w[(size_t)(kc + k) * HID + c * 4];
            Wd[k][c * 4 + 0] = dupf(v.x);
            Wd[k][c * 4 + 1] = dupf(v.y);
            Wd[k][c * 4 + 2] = dupf(v.z);
            Wd[k][c * 4 + 3] = dupf(v.w);
        }
        __syncthreads();
        #pragma unroll
        for (int k = 0; k < KC; k++) {
            const ull* ar = (const ull*)&As[k][rg * 8];
            ull a0 = ar[0], a1 = ar[1], a2 = ar[2], a3 = ar[3];
            ull w0 = Wd[k][og * 2], w1 = Wd[k][og * 2 + 1];
            acc[0][0] = ffma2(a0, w0, acc[0][0]);
            acc[0][1] = ffma2(a1, w0, acc[0][1]);
            acc[0][2] = ffma2(a2, w0, acc[0][2]);
            acc[0][3] = ffma2(a3, w0, acc[0][3]);
            acc[1][0] = ffma2(a0, w1, acc[1][0]);
            acc[1][1] = ffma2(a1, w1, acc[1][1]);
            acc[1][2] = ffma2(a2, w1, acc[1][2]);
            acc[1][3] = ffma2(a3, w1, acc[1][3]);
        }
    }
    __syncthreads();   // GEMM SMEM dead; safe to overwrite with Hs

    {
        const float bo0 = mlp_b[og * 2];
        const float bo1 = mlp_b[og * 2 + 1];
        #pragma unroll
        for (int rp = 0; rp < 4; rp++) {
            int r = rg * 8 + rp * 2;
            Hs[r    ][og * 2    ] = __uint_as_float((unsigned)(acc[0][rp]      )) + bo0;
            Hs[r + 1][og * 2    ] = __uint_as_float((unsigned)(acc[0][rp] >> 32)) + bo0;
            Hs[r    ][og * 2 + 1] = __uint_as_float((unsigned)(acc[1][rp]      )) + bo1;
            Hs[r + 1][og * 2 + 1] = __uint_as_float((unsigned)(acc[1][rp] >> 32)) + bo1;
        }
    }
    __syncthreads();

    // ---- KAN layer 0 (32 -> 6): 2 threads per row, 16 dims each ----
    {
        const int row  = tid >> 1;
        const int half = tid & 1;
        float acc6[W1] = {0.f, 0.f, 0.f, 0.f, 0.f, 0.f};
        #pragma unroll 1
        for (int ii = 0; ii < 16; ii++) {
            int i   = half * 16 + ii;
            float x = Hs[row][i];
            float B[16];
            basis12(x, B);
            float s = silu_f(x);
            #pragma unroll
            for (int o = 0; o < W1; o++) {
                float d = dot12(B, csc0[i][o]);
                acc6[o] = fmaf(s, wb0s[i][o], acc6[o] + d);
            }
        }
        #pragma unroll
        for (int o = 0; o < W1; o++) part[row][half][o] = acc6[o];
    }
    __syncthreads();

    // ---- KAN layer 1 (6 -> 1) + store ----
    if (tid < RPB) {
        const int row = tid;
        if (row0 + row < n) {
            float res = b1s;
            #pragma unroll 1
            for (int i = 0; i < W1; i++) {
                float x = part[row][0][i] + part[row][1][i] + b0s[i];
                float B[16];
                basis12(x, B);
                float d = dot12(B, csc1[i]);
                res += d + silu_f(x) * wb1s[i];
            }
            out[row0 + row] = res;
        }
    }
}

extern "C" void kernel_launch(void* const* d_in, const int* in_sizes, int n_in,
                              void* d_out, int out_size) {
    const float* node_rep = (const float*)d_in[0];
    const float* mlp_w    = (const float*)d_in[1];
    const float* mlp_b    = (const float*)d_in[2];
    const float* coef0    = (const float*)d_in[3];
    const float* wb0      = (const float*)d_in[4];
    const float* ws0      = (const float*)d_in[5];
    const float* b0       = (const float*)d_in[6];
    const float* coef1    = (const float*)d_in[7];
    const float* wb1      = (const float*)d_in[8];
    const float* ws1      = (const float*)d_in[9];
    const float* b1       = (const float*)d_in[10];

    int n = out_size;                       // 300000 rows, one output each
    int grid = (n + RPB - 1) / RPB;
    kan_fused_kernel<<<grid, NTHR>>>(node_rep, mlp_w, mlp_b, coef0, wb0, ws0,
                                     b0, coef1, wb1, ws1, b1,
                                     (float*)d_out, n);
}

// round 2
// speedup vs baseline: 1.1372x; 1.1372x over previous
#include <cuda_runtime.h>

typedef unsigned long long ull;

#define D_IN 992
#define HID  32
#define W1   6
#define NB   12
#define KC   32               // k-chunk
#define RPB  128              // rows per block
#define NTHR 256
#define NTILES (D_IN / KC)    // 31
#define ASTR 132              // float stride of As row (16B-aligned, padded)
#define WSTR 34               // ull stride of Wd row (16B-aligned, padded)

__device__ __forceinline__ ull ffma2(ull a, ull b, ull c) {
    ull d;
    asm("fma.rn.f32x2 %0, %1, %2, %3;" : "=l"(d) : "l"(a), "l"(b), "l"(c));
    return d;
}

__device__ __forceinline__ ull dupf(float f) {
    unsigned r = __float_as_uint(f);
    return (((ull)r) << 32) | (ull)r;
}

// Uniform-grid B-spline basis, G=8, K=4, knots t_j=(j-4)*0.25-1, j=0..16.
__device__ __forceinline__ void basis12(float x, float B[16]) {
    float u = (x + 2.0f) * 4.0f;
    int j0 = (int)floorf(u);
    #pragma unroll
    for (int j = 0; j < 16; j++) B[j] = (j == j0) ? 1.0f : 0.0f;
    #pragma unroll
    for (int p = 1; p <= 4; p++) {
        const float ip = 1.0f / (float)p;
        #pragma unroll
        for (int b = 0; b < 16 - p; b++)
            B[b] = ((u - (float)b) * B[b] + ((float)(b + p + 1) - u) * B[b + 1]) * ip;
    }
}

__device__ __forceinline__ float dot12(const float B[16], const float* __restrict__ c) {
    const float4* c4 = (const float4*)c;
    float4 a = c4[0], b = c4[1], d = c4[2];
    float s =      B[0]  * a.x;
    s = fmaf(B[1],  a.y, s); s = fmaf(B[2],  a.z, s); s = fmaf(B[3],  a.w, s);
    s = fmaf(B[4],  b.x, s); s = fmaf(B[5],  b.y, s); s = fmaf(B[6],  b.z, s);
    s = fmaf(B[7],  b.w, s); s = fmaf(B[8],  d.x, s); s = fmaf(B[9],  d.y, s);
    s = fmaf(B[10], d.z, s); s = fmaf(B[11], d.w, s);
    return s;
}

__device__ __forceinline__ float silu_f(float x) {
    return x / (1.0f + __expf(-x));
}

__global__ __launch_bounds__(NTHR, 2)
void kan_fused_kernel(const float* __restrict__ node_rep,
                      const float* __restrict__ mlp_w,
                      const float* __restrict__ mlp_b,
                      const float* __restrict__ coef0,
                      const float* __restrict__ wb0,
                      const float* __restrict__ ws0,
                      const float* __restrict__ b0,
                      const float* __restrict__ coef1,
                      const float* __restrict__ wb1,
                      const float* __restrict__ ws1,
                      const float* __restrict__ b1,
                      float* __restrict__ out, int n)
{
    // GEMM tiles (As + Wd) aliased with Hs: GEMM region dead once hidden done.
    // 25600 B >= 128*33*4 = 16896 B.
    __shared__ __align__(16) char buf[KC * ASTR * 4 + KC * WSTR * 8];
    float (*As)[ASTR]    = (float (*)[ASTR])buf;                    // [KC][132]
    ull   (*Wd)[WSTR]    = (ull   (*)[WSTR])(buf + KC * ASTR * 4);  // [KC][34] dup'd
    float (*Hs)[HID + 1] = (float (*)[HID + 1])buf;                 // [128][33]

    __shared__ __align__(16) float csc0[HID][W1][NB];   // coef0 * ws0
    __shared__ float wb0s[HID][W1];
    __shared__ float part[RPB][2][W1];
    __shared__ __align__(16) float csc1[W1][NB];        // coef1 * ws1
    __shared__ float wb1s[W1];
    __shared__ float b0s[W1];
    __shared__ float b1s;

    const int tid  = threadIdx.x;
    const int row0 = blockIdx.x * RPB;

    // ---- stage small params (prescale spline coefs by w_sp) ----
    for (int idx = tid; idx < HID * W1 * NB; idx += NTHR)
        (&csc0[0][0][0])[idx] = coef0[idx] * ws0[idx / NB];
    if (tid < HID * W1) (&wb0s[0][0])[tid] = wb0[tid];
    if (tid < W1 * NB)  (&csc1[0][0])[tid] = coef1[tid] * ws1[tid / NB];
    if (tid < W1) { wb1s[tid] = wb1[tid]; b0s[tid] = b0[tid]; }
    if (tid == 0) b1s = b1[0];

    // ---- GEMM: hidden[128][32] = node_rep_tile @ mlp_w ----
    const int og = tid & 15;   // output pair: cols og*2, og*2+1
    const int rg = tid >> 4;   // row group:   rows rg*8 .. rg*8+7
    ull acc[2][4];
    #pragma unroll
    for (int o = 0; o < 2; o++)
        #pragma unroll
        for (int r = 0; r < 4; r++) acc[o][r] = 0ull;

    // loader coordinates
    const int lc  = tid & 7;       // which float4 chunk of a row (k dim)
    const int lr0 = tid >> 3;      // base row (r = lr0 + 32j)
    const int wk  = tid >> 3;      // W: k row
    const int wc  = tid & 7;       // W: float4 chunk
    const int ssw = ((lc >> 1) & 1) * 8;   // store-side row swizzle (keyed on k>>3)

    float4 pa[4];
    float4 pw;

    // prologue: prefetch tile 0
    {
        #pragma unroll
        for (int j = 0; j < 4; j++) {
            int grow = row0 + lr0 + 32 * j;
            pa[j] = make_float4(0.f, 0.f, 0.f, 0.f);
            if (grow < n)
                pa[j] = *(const float4*)&node_rep[(size_t)grow * D_IN + lc * 4];
        }
        pw = *(const float4*)&mlp_w[(size_t)wk * HID + wc * 4];
    }

    for (int t = 0; t < NTILES; t++) {
        __syncthreads();                 // previous tile's compute done
        // ---- STS current tile (transpose A, dup W) ----
        #pragma unroll
        for (int j = 0; j < 4; j++) {
            int r = (lr0 + 32 * j) ^ ssw;
            As[lc * 4 + 0][r] = pa[j].x;
            As[lc * 4 + 1][r] = pa[j].y;
            As[lc * 4 + 2][r] = pa[j].z;
            As[lc * 4 + 3][r] = pa[j].w;
        }
        Wd[wk][wc * 4 + 0] = dupf(pw.x);
        Wd[wk][wc * 4 + 1] = dupf(pw.y);
        Wd[wk][wc * 4 + 2] = dupf(pw.z);
        Wd[wk][wc * 4 + 3] = dupf(pw.w);
        __syncthreads();

        // ---- prefetch next tile while computing this one ----
        if (t + 1 < NTILES) {
            const int kc = (t + 1) * KC;
            #pragma unroll
            for (int j = 0; j < 4; j++) {
                int grow = row0 + lr0 + 32 * j;
                float4 v = make_float4(0.f, 0.f, 0.f, 0.f);
                if (grow < n)
                    v = *(const float4*)&node_rep[(size_t)grow * D_IN + kc + lc * 4];
                pa[j] = v;
            }
            pw = *(const float4*)&mlp_w[(size_t)(kc + wk) * HID + wc * 4];
        }

        // ---- compute 32 k's ----
        #pragma unroll
        for (int g = 0; g < 4; g++) {
            const int rsw = (g & 1) * 8;
            const float* abase = &As[g * 8][(rg * 8) ^ rsw];
            const ull*   wbase = &Wd[g * 8][og * 2];
            #pragma unroll
            for (int kk = 0; kk < 8; kk++) {
                ulonglong2 alo = *(const ulonglong2*)(abase + kk * ASTR);
                ulonglong2 ahi = *(const ulonglong2*)(abase + kk * ASTR + 4);
                ulonglong2 wv  = *(const ulonglong2*)(wbase + kk * WSTR);
                ull a0 = alo.x, a1 = alo.y, a2 = ahi.x, a3 = ahi.y;
                ull w0 = wv.x,  w1 = wv.y;
                acc[0][0] = ffma2(a0, w0, acc[0][0]);
                acc[0][1] = ffma2(a1, w0, acc[0][1]);
                acc[0][2] = ffma2(a2, w0, acc[0][2]);
                acc[0][3] = ffma2(a3, w0, acc[0][3]);
                acc[1][0] = ffma2(a0, w1, acc[1][0]);
                acc[1][1] = ffma2(a1, w1, acc[1][1]);
                acc[1][2] = ffma2(a2, w1, acc[1][2]);
                acc[1][3] = ffma2(a3, w1, acc[1][3]);
            }
        }
    }
    __syncthreads();   // GEMM SMEM dead; safe to overwrite with Hs

    {
        const float bo0 = mlp_b[og * 2];
        const float bo1 = mlp_b[og * 2 + 1];
        #pragma unroll
        for (int rp = 0; rp < 4; rp++) {
            int r = rg * 8 + rp * 2;
            Hs[r    ][og * 2    ] = __uint_as_float((unsigned)(acc[0][rp]      )) + bo0;
            Hs[r + 1][og * 2    ] = __uint_as_float((unsigned)(acc[0][rp] >> 32)) + bo0;
            Hs[r    ][og * 2 + 1] = __uint_as_float((unsigned)(acc[1][rp]      )) + bo1;
            Hs[r + 1][og * 2 + 1] = __uint_as_float((unsigned)(acc[1][rp] >> 32)) + bo1;
        }
    }
    __syncthreads();

    // ---- KAN layer 0 (32 -> 6): 2 threads per row, 16 dims each ----
    {
        const int row  = tid >> 1;
        const int half = tid & 1;
        float acc6[W1] = {0.f, 0.f, 0.f, 0.f, 0.f, 0.f};
        #pragma unroll 1
        for (int ii = 0; ii < 16; ii++) {
            int i   = half * 16 + ii;
            float x = Hs[row][i];
            float B[16];
            basis12(x, B);
            float s = silu_f(x);
            #pragma unroll
            for (int o = 0; o < W1; o++) {
                float d = dot12(B, csc0[i][o]);
                acc6[o] = fmaf(s, wb0s[i][o], acc6[o] + d);
            }
        }
        #pragma unroll
        for (int o = 0; o < W1; o++) part[row][half][o] = acc6[o];
    }
    __syncthreads();

    // ---- KAN layer 1 (6 -> 1) + store ----
    if (tid < RPB) {
        const int row = tid;
        if (row0 + row < n) {
            float res = b1s;
            #pragma unroll 1
            for (int i = 0; i < W1; i++) {
                float x = part[row][0][i] + part[row][1][i] + b0s[i];
                float B[16];
                basis12(x, B);
                float d = dot12(B, csc1[i]);
                res += d + silu_f(x) * wb1s[i];
            }
            out[row0 + row] = res;
        }
    }
}

extern "C" void kernel_launch(void* const* d_in, const int* in_sizes, int n_in,
                              void* d_out, int out_size) {
    const float* node_rep = (const float*)d_in[0];
    const float* mlp_w    = (const float*)d_in[1];
    const float* mlp_b    = (const float*)d_in[2];
    const float* coef0    = (const float*)d_in[3];
    const float* wb0      = (const float*)d_in[4];
    const float* ws0      = (const float*)d_in[5];
    const float* b0       = (const float*)d_in[6];
    const float* coef1    = (const float*)d_in[7];
    const float* wb1      = (const float*)d_in[8];
    const float* ws1      = (const float*)d_in[9];
    const float* b1       = (const float*)d_in[10];

    int n = out_size;                       // 300000 rows, one output each
    int grid = (n + RPB - 1) / RPB;
    kan_fused_kernel<<<grid, NTHR>>>(node_rep, mlp_w, mlp_b, coef0, wb0, ws0,
                                     b0, coef1, wb1, ws1, b1,
                                     (float*)d_out, n);
}

// round 3
// speedup vs baseline: 1.1684x; 1.0274x over previous
#include <cuda_runtime.h>

typedef unsigned long long ull;

#define D_IN 992
#define HID  32
#define W1   6
#define NB   12
#define KC   32               // k-chunk
#define RPB  128              // rows per block
#define NTHR 256
#define NTILES (D_IN / KC)    // 31
#define ASTR 132              // float stride of As row (16B-aligned, padded)
#define WSTR 34               // ull stride of Wd row (16B-aligned, padded)

__device__ __forceinline__ ull ffma2(ull a, ull b, ull c) {
    ull d;
    asm("fma.rn.f32x2 %0, %1, %2, %3;" : "=l"(d) : "l"(a), "l"(b), "l"(c));
    return d;
}

__device__ __forceinline__ ull dupf(float f) {
    unsigned r = __float_as_uint(f);
    return (((ull)r) << 32) | (ull)r;
}

// Uniform-grid B-spline basis, G=8, K=4, knots t_j=(j-4)*0.25-1, j=0..16.
__device__ __forceinline__ void basis12(float x, float B[16]) {
    float u = (x + 2.0f) * 4.0f;
    int j0 = (int)floorf(u);
    #pragma unroll
    for (int j = 0; j < 16; j++) B[j] = (j == j0) ? 1.0f : 0.0f;
    #pragma unroll
    for (int p = 1; p <= 4; p++) {
        const float ip = 1.0f / (float)p;
        #pragma unroll
        for (int b = 0; b < 16 - p; b++)
            B[b] = ((u - (float)b) * B[b] + ((float)(b + p + 1) - u) * B[b + 1]) * ip;
    }
}

__device__ __forceinline__ float dot12(const float B[16], const float* __restrict__ c) {
    const float4* c4 = (const float4*)c;
    float4 a = c4[0], b = c4[1], d = c4[2];
    float s =      B[0]  * a.x;
    s = fmaf(B[1],  a.y, s); s = fmaf(B[2],  a.z, s); s = fmaf(B[3],  a.w, s);
    s = fmaf(B[4],  b.x, s); s = fmaf(B[5],  b.y, s); s = fmaf(B[6],  b.z, s);
    s = fmaf(B[7],  b.w, s); s = fmaf(B[8],  d.x, s); s = fmaf(B[9],  d.y, s);
    s = fmaf(B[10], d.z, s); s = fmaf(B[11], d.w, s);
    return s;
}

__device__ __forceinline__ float silu_f(float x) {
    return x / (1.0f + __expf(-x));
}

__global__ __launch_bounds__(NTHR, 2)
void kan_fused_kernel(const float* __restrict__ node_rep,
                      const float* __restrict__ mlp_w,
                      const float* __restrict__ mlp_b,
                      const float* __restrict__ coef0,
                      const float* __restrict__ wb0,
                      const float* __restrict__ ws0,
                      const float* __restrict__ b0,
                      const float* __restrict__ coef1,
                      const float* __restrict__ wb1,
                      const float* __restrict__ ws1,
                      const float* __restrict__ b1,
                      float* __restrict__ out, int n)
{
    // GEMM tiles (As + Wd) aliased with Hs: GEMM region dead once hidden done.
    // 25600 B >= 128*33*4 = 16896 B.
    __shared__ __align__(16) char buf[KC * ASTR * 4 + KC * WSTR * 8];
    float (*As)[ASTR]    = (float (*)[ASTR])buf;                    // [KC][132]
    ull   (*Wd)[WSTR]    = (ull   (*)[WSTR])(buf + KC * ASTR * 4);  // [KC][34] dup'd
    float (*Hs)[HID + 1] = (float (*)[HID + 1])buf;                 // [128][33]

    __shared__ __align__(16) float csc0[HID][W1][NB];   // coef0 * ws0
    __shared__ float wb0s[HID][W1];
    __shared__ float part[RPB][2][W1];
    __shared__ __align__(16) float csc1[W1][NB];        // coef1 * ws1
    __shared__ float wb1s[W1];
    __shared__ float b0s[W1];
    __shared__ float b1s;

    const int tid  = threadIdx.x;
    const int row0 = blockIdx.x * RPB;

    // ---- stage small params (prescale spline coefs by w_sp) ----
    for (int idx = tid; idx < HID * W1 * NB; idx += NTHR)
        (&csc0[0][0][0])[idx] = coef0[idx] * ws0[idx / NB];
    if (tid < HID * W1) (&wb0s[0][0])[tid] = wb0[tid];
    if (tid < W1 * NB)  (&csc1[0][0])[tid] = coef1[tid] * ws1[tid / NB];
    if (tid < W1) { wb1s[tid] = wb1[tid]; b0s[tid] = b0[tid]; }
    if (tid == 0) b1s = b1[0];

    // ---- GEMM: hidden[128][32] = node_rep_tile @ mlp_w ----
    const int og = tid & 15;   // output pair: cols og*2, og*2+1
    const int rg = tid >> 4;   // row group:   rows rg*8 .. rg*8+7
    ull acc[2][4];
    #pragma unroll
    for (int o = 0; o < 2; o++)
        #pragma unroll
        for (int r = 0; r < 4; r++) acc[o][r] = 0ull;

    // loader coordinates
    const int lc  = tid & 7;       // which float4 chunk of a row (k dim)
    const int lr0 = tid >> 3;      // base row (r = lr0 + 32j)
    const int wk  = tid >> 3;      // W: k row
    const int wc  = tid & 7;       // W: float4 chunk
    const int ssw = ((lc >> 1) & 1) * 8;   // store-side row swizzle (keyed on k>>3)

    float4 pa[4];
    float4 pw;

    // prologue: prefetch tile 0
    {
        #pragma unroll
        for (int j = 0; j < 4; j++) {
            int grow = row0 + lr0 + 32 * j;
            pa[j] = make_float4(0.f, 0.f, 0.f, 0.f);
            if (grow < n)
                pa[j] = *(const float4*)&node_rep[(size_t)grow * D_IN + lc * 4];
        }
        pw = *(const float4*)&mlp_w[(size_t)wk * HID + wc * 4];
    }

    for (int t = 0; t < NTILES; t++) {
        __syncthreads();                 // previous tile's compute done
        // ---- STS current tile (transpose A, dup W) ----
        #pragma unroll
        for (int j = 0; j < 4; j++) {
            int r = (lr0 + 32 * j) ^ ssw;
            As[lc * 4 + 0][r] = pa[j].x;
            As[lc * 4 + 1][r] = pa[j].y;
            As[lc * 4 + 2][r] = pa[j].z;
            As[lc * 4 + 3][r] = pa[j].w;
        }
        Wd[wk][wc * 4 + 0] = dupf(pw.x);
        Wd[wk][wc * 4 + 1] = dupf(pw.y);
        Wd[wk][wc * 4 + 2] = dupf(pw.z);
        Wd[wk][wc * 4 + 3] = dupf(pw.w);
        __syncthreads();

        // ---- prefetch next tile while computing this one ----
        if (t + 1 < NTILES) {
            const int kc = (t + 1) * KC;
            #pragma unroll
            for (int j = 0; j < 4; j++) {
                int grow = row0 + lr0 + 32 * j;
                float4 v = make_float4(0.f, 0.f, 0.f, 0.f);
                if (grow < n)
                    v = *(const float4*)&node_rep[(size_t)grow * D_IN + kc + lc * 4];
                pa[j] = v;
            }
            pw = *(const float4*)&mlp_w[(size_t)(kc + wk) * HID + wc * 4];
        }

        // ---- compute 32 k's ----
        #pragma unroll
        for (int g = 0; g < 4; g++) {
            const int rsw = (g & 1) * 8;
            const float* abase = &As[g * 8][(rg * 8) ^ rsw];
            const ull*   wbase = &Wd[g * 8][og * 2];
            #pragma unroll
            for (int kk = 0; kk < 8; kk++) {
                ulonglong2 alo = *(const ulonglong2*)(abase + kk * ASTR);
                ulonglong2 ahi = *(const ulonglong2*)(abase + kk * ASTR + 4);
                ulonglong2 wv  = *(const ulonglong2*)(wbase + kk * WSTR);
                ull a0 = alo.x, a1 = alo.y, a2 = ahi.x, a3 = ahi.y;
                ull w0 = wv.x,  w1 = wv.y;
                acc[0][0] = ffma2(a0, w0, acc[0][0]);
                acc[0][1] = ffma2(a1, w0, acc[0][1]);
                acc[0][2] = ffma2(a2, w0, acc[0][2]);
                acc[0][3] = ffma2(a3, w0, acc[0][3]);
                acc[1][0] = ffma2(a0, w1, acc[1][0]);
                acc[1][1] = ffma2(a1, w1, acc[1][1]);
                acc[1][2] = ffma2(a2, w1, acc[1][2]);
                acc[1][3] = ffma2(a3, w1, acc[1][3]);
            }
        }
    }
    __syncthreads();   // GEMM SMEM dead; safe to overwrite with Hs

    {
        const float bo0 = mlp_b[og * 2];
        const float bo1 = mlp_b[og * 2 + 1];
        #pragma unroll
        for (int rp = 0; rp < 4; rp++) {
            int r = rg * 8 + rp * 2;
            Hs[r    ][og * 2    ] = __uint_as_float((unsigned)(acc[0][rp]      )) + bo0;
            Hs[r + 1][og * 2    ] = __uint_as_float((unsigned)(acc[0][rp] >> 32)) + bo0;
            Hs[r    ][og * 2 + 1] = __uint_as_float((unsigned)(acc[1][rp]      )) + bo1;
            Hs[r + 1][og * 2 + 1] = __uint_as_float((unsigned)(acc[1][rp] >> 32)) + bo1;
        }
    }
    __syncthreads();

    // ---- KAN layer 0 (32 -> 6): 2 threads per row, 16 dims each ----
    {
        const int row  = tid >> 1;
        const int half = tid & 1;
        float acc6[W1] = {0.f, 0.f, 0.f, 0.f, 0.f, 0.f};
        #pragma unroll 1
        for (int ii = 0; ii < 16; ii++) {
            int i   = half * 16 + ii;
            float x = Hs[row][i];
            float B[16];
            basis12(x, B);
            float s = silu_f(x);
            #pragma unroll
            for (int o = 0; o < W1; o++) {
                float d = dot12(B, csc0[i][o]);
                acc6[o] = fmaf(s, wb0s[i][o], acc6[o] + d);
            }
        }
        #pragma unroll
        for (int o = 0; o < W1; o++) part[row][half][o] = acc6[o];
    }
    __syncthreads();

    // ---- KAN layer 1 (6 -> 1) + store ----
    if (tid < RPB) {
        const int row = tid;
        if (row0 + row < n) {
            float res = b1s;
            #pragma unroll 1
            for (int i = 0; i < W1; i++) {
                float x = part[row][0][i] + part[row][1][i] + b0s[i];
                float B[16];
                basis12(x, B);
                float d = dot12(B, csc1[i]);
                res += d + silu_f(x) * wb1s[i];
            }
            out[row0 + row] = res;
        }
    }
}

extern "C" void kernel_launch(void* const* d_in, const int* in_sizes, int n_in,
                              void* d_out, int out_size) {
    const float* node_rep = (const float*)d_in[0];
    const float* mlp_w    = (const float*)d_in[1];
    const float* mlp_b    = (const float*)d_in[2];
    const float* coef0    = (const float*)d_in[3];
    const float* wb0      = (const float*)d_in[4];
    const float* ws0      = (const float*)d_in[5];
    const float* b0       = (const float*)d_in[6];
    const float* coef1    = (const float*)d_in[7];
    const float* wb1      = (const float*)d_in[8];
    const float* ws1      = (const float*)d_in[9];
    const float* b1       = (const float*)d_in[10];

    int n = out_size;                       // 300000 rows, one output each
    int grid = (n + RPB - 1) / RPB;
    kan_fused_kernel<<<grid, NTHR>>>(node_rep, mlp_w, mlp_b, coef0, wb0, ws0,
                                     b0, coef1, wb1, ws1, b1,
                                     (float*)d_out, n);
}